// round 2
// baseline (speedup 1.0000x reference)
#include <cuda_runtime.h>

#define FDIM    128
#define TP      128     // points per CTA tile
#define NTHR    256
#define NLAYERS 8
#define OMEGA_W 30.0f

// Pre-transposed weights: WT[k][j] = W[j][k], so the GEMM k-loop reads
// j-contiguous float4 fragments from smem conflict-free.
__device__ float g_WT1[NLAYERS][FDIM * FDIM];
__device__ float g_WT2[NLAYERS][FDIM * FDIM];

__global__ void transpose_weights_kernel(const float* __restrict__ W1,
                                         const float* __restrict__ W2) {
    int layer = blockIdx.x;
    const float* src = (blockIdx.y == 0 ? W1 : W2) + layer * FDIM * FDIM;
    float* dst = (blockIdx.y == 0 ? g_WT1[layer] : g_WT2[layer]);
    for (int t = threadIdx.x; t < FDIM * FDIM; t += blockDim.x) {
        int j = t >> 7;          // row in source  [j][k]
        int k = t & 127;         // col in source
        dst[k * FDIM + j] = src[t];
    }
}

// 128x128x128 smem GEMM microkernel: acc[i][q] = sum_k A[k][j0+i] * B[k][p0+q]
// A = transposed weights [k][FDIM], B = activations [k][TP].
__device__ __forceinline__ void gemm128(const float* __restrict__ swA,
                                        const float* __restrict__ sxB,
                                        int j0, int p0, float acc[8][8]) {
#pragma unroll
    for (int i = 0; i < 8; i++)
#pragma unroll
        for (int q = 0; q < 8; q++) acc[i][q] = 0.f;

#pragma unroll 8
    for (int k = 0; k < FDIM; k++) {
        float wf[8], xf[8];
        *(float4*)&wf[0] = *(const float4*)&swA[k * FDIM + j0];
        *(float4*)&wf[4] = *(const float4*)&swA[k * FDIM + j0 + 4];
        *(float4*)&xf[0] = *(const float4*)&sxB[k * TP + p0];
        *(float4*)&xf[4] = *(const float4*)&sxB[k * TP + p0 + 4];
#pragma unroll
        for (int i = 0; i < 8; i++)
#pragma unroll
            for (int q = 0; q < 8; q++)
                acc[i][q] = fmaf(wf[i], xf[q], acc[i][q]);
    }
}

__global__ __launch_bounds__(NTHR, 1)
void siren_kernel(const float* __restrict__ coords,
                  const float* __restrict__ W_first,
                  const float* __restrict__ b_first,
                  const float* __restrict__ b1,
                  const float* __restrict__ b2,
                  const float* __restrict__ W_out,
                  const float* __restrict__ b_out,
                  float* __restrict__ out, int N) {
    extern __shared__ float smem[];
    float* sh = smem;                    // h  [FDIM][TP]   64 KB
    float* ss = smem + FDIM * TP;        // s1 [FDIM][TP]   64 KB
    float* sw = smem + 2 * FDIM * TP;    // W  [k][j]       64 KB

    const int tid = threadIdx.x;
    const int tx  = tid & 15;            // point-group
    const int ty  = tid >> 4;            // feature-group
    const int p0  = tx * 8;
    const int j0  = ty * 8;
    const int P0  = blockIdx.x * TP;

    // ---- stage coords (ss[d][p]) and W_first^T (sw[d][j]) ----
    for (int t = tid; t < 3 * TP; t += NTHR) {
        int pi = t / 3, d = t % 3;
        int pg = min(P0 + pi, N - 1);    // clamp for partial last block
        ss[d * TP + pi] = coords[pg * 3 + d];
    }
    for (int t = tid; t < 3 * FDIM; t += NTHR) {
        int j = t / 3, d = t % 3;
        sw[d * FDIM + j] = W_first[j * 3 + d];
    }
    __syncthreads();

    // ---- first SIREN layer: h = sin(omega * (W_first x + b_first)) ----
    {
        float acc[8][8];
#pragma unroll
        for (int i = 0; i < 8; i++)
#pragma unroll
            for (int q = 0; q < 8; q++) acc[i][q] = 0.f;
#pragma unroll
        for (int d = 0; d < 3; d++) {
            float wf[8], xf[8];
#pragma unroll
            for (int i = 0; i < 8; i++) wf[i] = sw[d * FDIM + j0 + i];
#pragma unroll
            for (int q = 0; q < 8; q++) xf[q] = ss[d * TP + p0 + q];
#pragma unroll
            for (int i = 0; i < 8; i++)
#pragma unroll
                for (int q = 0; q < 8; q++)
                    acc[i][q] = fmaf(wf[i], xf[q], acc[i][q]);
        }
#pragma unroll
        for (int i = 0; i < 8; i++) {
            float b = __ldg(&b_first[j0 + i]);
#pragma unroll
            for (int q = 0; q < 8; q++)
                sh[(j0 + i) * TP + p0 + q] = __sinf(OMEGA_W * (acc[i][q] + b));
        }
    }
    __syncthreads();

    // ---- 8 residual sin-blocks ----
    for (int layer = 0; layer < NLAYERS; layer++) {
        const float w_in  = (layer > 0) ? 0.5f : 1.0f;
        const float w_out = (layer == NLAYERS - 1) ? 0.5f : 1.0f;

        // stage W1[layer]^T
        {
            const float4* src = (const float4*)g_WT1[layer];
            float4* dst = (float4*)sw;
            for (int t = tid; t < (FDIM * FDIM) / 4; t += NTHR) dst[t] = src[t];
        }
        __syncthreads();

        float acc[8][8];
        gemm128(sw, sh, j0, p0, acc);      // (w_in*h) @ W1^T : scale folded below
#pragma unroll
        for (int i = 0; i < 8; i++) {
            float b = __ldg(&b1[layer * FDIM + j0 + i]);
#pragma unroll
            for (int q = 0; q < 8; q++)
                ss[(j0 + i) * TP + p0 + q] =
                    __sinf(OMEGA_W * fmaf(w_in, acc[i][q], b));
        }
        __syncthreads();   // ss complete; sw free

        // stage W2[layer]^T
        {
            const float4* src = (const float4*)g_WT2[layer];
            float4* dst = (float4*)sw;
            for (int t = tid; t < (FDIM * FDIM) / 4; t += NTHR) dst[t] = src[t];
        }
        __syncthreads();

        gemm128(sw, ss, j0, p0, acc);      // s1 @ W2^T
#pragma unroll
        for (int i = 0; i < 8; i++) {
            float b = __ldg(&b2[layer * FDIM + j0 + i]);
#pragma unroll
            for (int q = 0; q < 8; q++) {
                float s2 = __sinf(OMEGA_W * (acc[i][q] + b));
                int idx = (j0 + i) * TP + p0 + q;
                sh[idx] = w_out * (sh[idx] + s2);   // residual, exclusively owned
            }
        }
        __syncthreads();
    }

    // ---- output layer: y[p] = h[:,p] . W_out + b_out ----
    if (tid < TP) {
        int p = tid;
        if (P0 + p < N) {
            float sum = __ldg(&b_out[0]);
#pragma unroll 8
            for (int j = 0; j < FDIM; j++)
                sum = fmaf(sh[j * TP + p], __ldg(&W_out[j]), sum);
            out[P0 + p] = sum;
        }
    }
}

extern "C" void kernel_launch(void* const* d_in, const int* in_sizes, int n_in,
                              void* d_out, int out_size) {
    const float* coords  = (const float*)d_in[0];
    const float* W_first = (const float*)d_in[1];
    const float* b_first = (const float*)d_in[2];
    const float* W1      = (const float*)d_in[3];
    const float* b1      = (const float*)d_in[4];
    const float* W2      = (const float*)d_in[5];
    const float* b2      = (const float*)d_in[6];
    const float* W_out   = (const float*)d_in[7];
    const float* b_out   = (const float*)d_in[8];
    const int N = in_sizes[0] / 3;

    // One-shot weight transpose into device scratch (runs every call; ~2 MB, us-scale)
    transpose_weights_kernel<<<dim3(NLAYERS, 2), 256>>>(W1, W2);

    const size_t smem_bytes = (size_t)(2 * FDIM * TP + FDIM * FDIM) * sizeof(float); // 192 KB
    cudaFuncSetAttribute(siren_kernel,
                         cudaFuncAttributeMaxDynamicSharedMemorySize,
                         (int)smem_bytes);

    const int nblocks = (N + TP - 1) / TP;
    siren_kernel<<<nblocks, NTHR, smem_bytes>>>(coords, W_first, b_first,
                                                b1, b2, W_out, b_out,
                                                (float*)d_out, N);
}

// round 4
// speedup vs baseline: 2.7791x; 2.7791x over previous
#include <cuda_runtime.h>
#include <cuda_bf16.h>
#include <cstdint>

#define FDIM    128
#define TP      128
#define NTHR    256
#define NLAYERS 8
#define NGEMM   16
#define OMEGA_W 30.0f

// ---------------- smem layout (bytes) ----------------
#define SMEM_MB_W0   0
#define SMEM_MB_W1   8
#define SMEM_CS      64                    // 128*3 floats coords (1536 B)
#define SMEM_XHI     2048                  // activations hi [128 f][128 n] bf16, 32 KB
#define SMEM_XLO     (2048 + 32768)        // activations lo, 32 KB
#define SMEM_WBUF0   67584                 // weight buf 0: hi 32K + lo 32K
#define SMEM_WBUF1   133120                // weight buf 1
#define SMEM_YBUF    67584                 // overlays WBUF0 (free after g=14 MMA)
#define SMEM_TOTAL   198656

// Pre-split, pre-swizzled weights: [gemm][hi/lo][128*128] bf16
__device__ __align__(128) __nv_bfloat16 g_W[NGEMM][2][FDIM * FDIM];

// ---------------- PTX helpers (base sm_90 / sm_80 features only) ----------------
__device__ __forceinline__ uint32_t smem_u32(const void* p) {
    uint32_t a;
    asm("{ .reg .u64 t; cvta.to.shared.u64 t, %1; cvt.u32.u64 %0, t; }" : "=r"(a) : "l"(p));
    return a;
}
#define MBAR_INIT(mbar, cnt) \
    asm volatile("mbarrier.init.shared.b64 [%0], %1;" :: "r"(mbar), "r"(cnt) : "memory")
#define MBAR_EXPECT_TX(mbar, bytes) \
    asm volatile("mbarrier.arrive.expect_tx.shared.b64 _, [%0], %1;" :: "r"(mbar), "r"(bytes) : "memory")
#define MBAR_WAIT(mbar, ph) do {                                              \
    asm volatile("{\n\t.reg .pred P1;\n\t"                                    \
        "WL_%=:\n\t"                                                          \
        "mbarrier.try_wait.parity.acquire.cta.shared::cta.b64 P1, [%0], %1, 0x989680;\n\t" \
        "@P1 bra.uni WD_%=;\n\t"                                              \
        "bra.uni WL_%=;\n\t"                                                  \
        "WD_%=:\n\t}"                                                         \
        :: "r"(mbar), "r"(ph) : "memory");                                    \
} while (0)
#define BULK_G2S(dst, src, bytes, mbar) \
    asm volatile("cp.async.bulk.shared::cluster.global.mbarrier::complete_tx::bytes [%0], [%1], %2, [%3];" \
        :: "r"(dst), "l"(src), "r"(bytes), "r"(mbar) : "memory")

#define LDSM_X4(r, addr) \
    asm volatile("ldmatrix.sync.aligned.m8n8.x4.shared.b16 {%0,%1,%2,%3}, [%4];" \
        : "=r"((r)[0]), "=r"((r)[1]), "=r"((r)[2]), "=r"((r)[3]) : "r"(addr))
#define LDSM_X4T(r, addr) \
    asm volatile("ldmatrix.sync.aligned.m8n8.x4.trans.shared.b16 {%0,%1,%2,%3}, [%4];" \
        : "=r"((r)[0]), "=r"((r)[1]), "=r"((r)[2]), "=r"((r)[3]) : "r"(addr))

#define MMA16816(d, a, b0, b1) \
    asm volatile("mma.sync.aligned.m16n8k16.row.col.f32.bf16.bf16.f32 " \
        "{%0,%1,%2,%3},{%4,%5,%6,%7},{%8,%9},{%0,%1,%2,%3};" \
        : "+f"((d)[0]), "+f"((d)[1]), "+f"((d)[2]), "+f"((d)[3]) \
        : "r"((a)[0]), "r"((a)[1]), "r"((a)[2]), "r"((a)[3]), "r"(b0), "r"(b1))

// XOR swizzle: tile rows are 256 B (128 bf16); (f,n) -> byte offset, conflict-free
// for ldmatrix row fetches and for the epilogue's 4B paired stores.
__device__ __forceinline__ uint32_t xoff(int f, int n) {
    return (uint32_t)(f * 256 + ((2 * n) ^ ((f & 7) << 4)));
}

// split fp32 -> bf16 hi/lo pair and store both halves for points (n, n+1)
__device__ __forceinline__ void store_split(char* smemc, int f, int n, float v0, float v1) {
    uint32_t off = xoff(f, n);
    __nv_bfloat162 hi = __floats2bfloat162_rn(v0, v1);
    float r0 = v0 - __low2float(hi);
    float r1 = v1 - __high2float(hi);
    __nv_bfloat162 lo = __floats2bfloat162_rn(r0, r1);
    *reinterpret_cast<__nv_bfloat162*>(smemc + SMEM_XHI + off) = hi;
    *reinterpret_cast<__nv_bfloat162*>(smemc + SMEM_XLO + off) = lo;
}

// ---------------- weight prep: fp32 -> split bf16 hi/lo, swizzled ----------------
__global__ void prep_weights_kernel(const float* __restrict__ W1,
                                    const float* __restrict__ W2) {
    int g = blockIdx.x;
    int layer = g >> 1;
    const float* src = ((g & 1) ? W2 : W1) + layer * FDIM * FDIM;
    for (int idx = threadIdx.x; idx < FDIM * FDIM; idx += blockDim.x) {
        int f = idx >> 7;               // out feature (M)
        int k = idx & 127;              // in feature (K)
        float w = src[idx];
        __nv_bfloat16 hi = __float2bfloat16(w);
        __nv_bfloat16 lo = __float2bfloat16(w - __bfloat162float(hi));
        uint32_t e = (uint32_t)(f * FDIM + (k ^ ((f & 7) << 3)));
        g_W[g][0][e] = hi;
        g_W[g][1][e] = lo;
    }
}

// ---------------- main kernel ----------------
__global__ __launch_bounds__(NTHR, 1)
void siren_mma_kernel(const float* __restrict__ coords,
                      const float* __restrict__ W_first,
                      const float* __restrict__ b_first,
                      const float* __restrict__ b1,
                      const float* __restrict__ b2,
                      const float* __restrict__ W_out,
                      const float* __restrict__ b_out,
                      float* __restrict__ out, int N) {
    extern __shared__ char smem[];
    const uint32_t sb = smem_u32(smem);
    float* cs = (float*)(smem + SMEM_CS);

    const int tid  = threadIdx.x;
    const int w    = tid >> 5;
    const int lane = tid & 31;
    const int f0   = w << 4;               // warp owns features [f0, f0+16)
    const int tg   = lane >> 2;            // 0..7 (row-in-tile group)
    const int t4   = lane & 3;             // 0..3 (col pair select)
    const int r0   = f0 + tg;              // this thread's feature rows
    const int r1   = r0 + 8;
    const int P0   = blockIdx.x * TP;

    // ldmatrix lane addressing components
    const int li = lane >> 3;              // matrix select 0..3
    const int lr = lane & 7;               // row within 8x8

    if (tid == 0) {
        MBAR_INIT(sb + SMEM_MB_W0, 1);
        MBAR_INIT(sb + SMEM_MB_W1, 1);
    }
    // stage coords [p][3]
    for (int t = tid; t < 3 * TP; t += NTHR) {
        int p = t / 3, d = t - p * 3;
        int pg = min(P0 + p, N - 1);
        cs[t] = coords[pg * 3 + d];
    }
    __syncthreads();

    // prefetch weights for GEMM 0 and 1
    if (tid == 0) {
        MBAR_EXPECT_TX(sb + SMEM_MB_W0, 65536u);
        BULK_G2S(sb + SMEM_WBUF0, (const void*)&g_W[0][0][0], 65536u, sb + SMEM_MB_W0);
        MBAR_EXPECT_TX(sb + SMEM_MB_W1, 65536u);
        BULK_G2S(sb + SMEM_WBUF1, (const void*)&g_W[1][0][0], 65536u, sb + SMEM_MB_W1);
    }

    float h[16][4];                        // residual, c-frag layout: {r0p0,r0p1,r1p0,r1p1}

    // ---- first layer: h = sin(30*(W_first x + b_first)), K=3 via FFMA ----
    {
        const float wa0 = __ldg(&W_first[r0 * 3]),     wa1 = __ldg(&W_first[r0 * 3 + 1]),
                    wa2 = __ldg(&W_first[r0 * 3 + 2]);
        const float wb0 = __ldg(&W_first[r1 * 3]),     wb1 = __ldg(&W_first[r1 * 3 + 1]),
                    wb2 = __ldg(&W_first[r1 * 3 + 2]);
        const float ba = __ldg(&b_first[r0]), bb = __ldg(&b_first[r1]);
#pragma unroll
        for (int j = 0; j < 16; j++) {
            int pb = 8 * j + t4 * 2;
            float x0 = cs[pb * 3], y0 = cs[pb * 3 + 1], z0 = cs[pb * 3 + 2];
            float x1 = cs[pb * 3 + 3], y1 = cs[pb * 3 + 4], z1 = cs[pb * 3 + 5];
            h[j][0] = __sinf(OMEGA_W * fmaf(wa0, x0, fmaf(wa1, y0, fmaf(wa2, z0, ba))));
            h[j][1] = __sinf(OMEGA_W * fmaf(wa0, x1, fmaf(wa1, y1, fmaf(wa2, z1, ba))));
            h[j][2] = __sinf(OMEGA_W * fmaf(wb0, x0, fmaf(wb1, y0, fmaf(wb2, z0, bb))));
            h[j][3] = __sinf(OMEGA_W * fmaf(wb0, x1, fmaf(wb1, y1, fmaf(wb2, z1, bb))));
            store_split(smem, r0, pb, h[j][0], h[j][1]);
            store_split(smem, r1, pb, h[j][2], h[j][3]);
        }
    }
    __syncthreads();

    int wph0 = 0, wph1 = 0;

    for (int g = 0; g < NGEMM; g++) {
        const int layer = g >> 1;

        // wait for this GEMM's weight buffer (all threads)
        {
            uint32_t mb = sb + ((g & 1) ? SMEM_MB_W1 : SMEM_MB_W0);
            int ph = (g & 1) ? wph1 : wph0;
            MBAR_WAIT(mb, ph);
            if (g & 1) wph1 ^= 1; else wph0 ^= 1;
        }

        const uint32_t wbase = sb + ((g & 1) ? SMEM_WBUF1 : SMEM_WBUF0);
        const uint32_t xhi = sb + SMEM_XHI, xlo = sb + SMEM_XLO;

        float d[16][4];
#pragma unroll
        for (int j = 0; j < 16; j++) { d[j][0] = d[j][1] = d[j][2] = d[j][3] = 0.f; }

        // ---- 3-way split MMA: Whi*Xhi + Whi*Xlo + Wlo*Xhi ----
#pragma unroll
        for (int kk = 0; kk < 8; kk++) {
            const int k0 = kk << 4;
            // A fragments (weights, rows f0..f0+15, cols k0..k0+15)
            const int arow = f0 + ((li & 1) << 3) + lr;
            const int acol = k0 + ((li >> 1) << 3);
            const uint32_t aoff = xoff(arow, acol);
            uint32_t ahi[4], alo[4];
            LDSM_X4(ahi, wbase + aoff);
            LDSM_X4(alo, wbase + 32768u + aoff);

#pragma unroll
            for (int nh = 0; nh < 2; nh++) {
                uint32_t bh[4][4], bl[4][4];
#pragma unroll
                for (int q = 0; q < 4; q++) {
                    const int m = nh * 4 + q;                       // n16 group
                    const int krow = k0 + ((li & 1) << 3) + lr;
                    const int ncol = m * 16 + ((li >> 1) << 3);
                    const uint32_t boff = xoff(krow, ncol);
                    LDSM_X4T(bh[q], xhi + boff);
                    LDSM_X4T(bl[q], xlo + boff);
                }
#pragma unroll
                for (int q = 0; q < 4; q++) {
                    const int m = nh * 4 + q;
                    MMA16816(d[2 * m],     ahi, bh[q][0], bh[q][1]);
                    MMA16816(d[2 * m + 1], ahi, bh[q][2], bh[q][3]);
                    MMA16816(d[2 * m],     ahi, bl[q][0], bl[q][1]);
                    MMA16816(d[2 * m + 1], ahi, bl[q][2], bl[q][3]);
                    MMA16816(d[2 * m],     alo, bh[q][0], bh[q][1]);
                    MMA16816(d[2 * m + 1], alo, bh[q][2], bh[q][3]);
                }
            }
        }

        __syncthreads();   // X + W fully consumed

        // prefetch weights for g+2 into the buffer just freed
        if (tid == 0 && g + 2 < NGEMM) {
            uint32_t mb = sb + ((g & 1) ? SMEM_MB_W1 : SMEM_MB_W0);
            uint32_t wb = sb + ((g & 1) ? SMEM_WBUF1 : SMEM_WBUF0);
            MBAR_EXPECT_TX(mb, 65536u);
            BULK_G2S(wb, (const void*)&g_W[g + 2][0][0], 65536u, mb);
        }

        if ((g & 1) == 0) {
            // ---- s1 = sin(30*(w_in*D + b1)) -> X ----
            const float w_in = (layer > 0) ? 0.5f : 1.0f;
            const float ba = __ldg(&b1[layer * FDIM + r0]);
            const float bb = __ldg(&b1[layer * FDIM + r1]);
#pragma unroll
            for (int j = 0; j < 16; j++) {
                int pb = 8 * j + t4 * 2;
                float s00 = __sinf(OMEGA_W * fmaf(w_in, d[j][0], ba));
                float s01 = __sinf(OMEGA_W * fmaf(w_in, d[j][1], ba));
                float s10 = __sinf(OMEGA_W * fmaf(w_in, d[j][2], bb));
                float s11 = __sinf(OMEGA_W * fmaf(w_in, d[j][3], bb));
                store_split(smem, r0, pb, s00, s01);
                store_split(smem, r1, pb, s10, s11);
            }
        } else if (g < NGEMM - 1) {
            // ---- s2 = sin(30*(D + b2)); h = w_out*(h + s2) -> X ----
            const float ba = __ldg(&b2[layer * FDIM + r0]);
            const float bb = __ldg(&b2[layer * FDIM + r1]);
#pragma unroll
            for (int j = 0; j < 16; j++) {
                int pb = 8 * j + t4 * 2;
                h[j][0] = h[j][0] + __sinf(OMEGA_W * (d[j][0] + ba));
                h[j][1] = h[j][1] + __sinf(OMEGA_W * (d[j][1] + ba));
                h[j][2] = h[j][2] + __sinf(OMEGA_W * (d[j][2] + bb));
                h[j][3] = h[j][3] + __sinf(OMEGA_W * (d[j][3] + bb));
                store_split(smem, r0, pb, h[j][0], h[j][1]);
                store_split(smem, r1, pb, h[j][2], h[j][3]);
            }
        } else {
            // ---- final block: h = 0.5*(h + s2); then output GEMV in-register ----
            const float ba = __ldg(&b2[layer * FDIM + r0]);
            const float bb = __ldg(&b2[layer * FDIM + r1]);
            const float wo0 = __ldg(&W_out[r0]), wo1 = __ldg(&W_out[r1]);
            float* ybuf = (float*)(smem + SMEM_YBUF);
#pragma unroll
            for (int j = 0; j < 16; j++) {
                float h0 = 0.5f * (h[j][0] + __sinf(OMEGA_W * (d[j][0] + ba)));
                float h1 = 0.5f * (h[j][1] + __sinf(OMEGA_W * (d[j][1] + ba)));
                float h2 = 0.5f * (h[j][2] + __sinf(OMEGA_W * (d[j][2] + bb)));
                float h3 = 0.5f * (h[j][3] + __sinf(OMEGA_W * (d[j][3] + bb)));
                float p0 = fmaf(h0, wo0, h2 * wo1);      // partial y at point 8j+2*t4
                float p1 = fmaf(h1, wo0, h3 * wo1);      // partial y at point 8j+2*t4+1
#pragma unroll
                for (int m = 4; m <= 16; m <<= 1) {      // reduce over tg (rows)
                    p0 += __shfl_xor_sync(0xffffffffu, p0, m);
                    p1 += __shfl_xor_sync(0xffffffffu, p1, m);
                }
                if (tg == 0) {
                    int p = 8 * j + t4 * 2;
                    *reinterpret_cast<float2*>(&ybuf[w * TP + p]) = make_float2(p0, p1);
                }
            }
        }
        __syncthreads();
    }

    // ---- cross-warp output reduction ----
    if (tid < TP) {
        int p = tid;
        if (P0 + p < N) {
            float* ybuf = (float*)(smem + SMEM_YBUF);
            float y = __ldg(&b_out[0]);
#pragma unroll
            for (int ww = 0; ww < 8; ww++) y += ybuf[ww * TP + p];
            out[P0 + p] = y;
        }
    }
}

extern "C" void kernel_launch(void* const* d_in, const int* in_sizes, int n_in,
                              void* d_out, int out_size) {
    const float* coords  = (const float*)d_in[0];
    const float* W_first = (const float*)d_in[1];
    const float* b_first = (const float*)d_in[2];
    const float* W1      = (const float*)d_in[3];
    const float* b1      = (const float*)d_in[4];
    const float* W2      = (const float*)d_in[5];
    const float* b2      = (const float*)d_in[6];
    const float* W_out   = (const float*)d_in[7];
    const float* b_out   = (const float*)d_in[8];
    const int N = in_sizes[0] / 3;

    prep_weights_kernel<<<NGEMM, 256>>>(W1, W2);

    cudaFuncSetAttribute(siren_mma_kernel,
                         cudaFuncAttributeMaxDynamicSharedMemorySize, SMEM_TOTAL);

    const int nblocks = (N + TP - 1) / TP;
    siren_mma_kernel<<<nblocks, NTHR, SMEM_TOTAL>>>(coords, W_first, b_first,
                                                    b1, b2, W_out, b_out,
                                                    (float*)d_out, N);
}

// round 5
// speedup vs baseline: 2.7821x; 1.0011x over previous
#include <cuda_runtime.h>
#include <cuda_bf16.h>
#include <cstdint>

#define FDIM    128
#define TP      128
#define NTHR    256
#define NLAYERS 8
#define NGEMM   16
#define OMEGA_W 30.0f

// ---------------- smem layout (bytes) ----------------
#define SMEM_MB_W0   0
#define SMEM_MB_W1   8
#define SMEM_CS      64                    // 128*3 floats coords (1536 B)
#define SMEM_XH0A    2048                  // X half0 buf A: hi 16K + lo 16K
#define SMEM_XH0B    34816                 // X half0 buf B
#define SMEM_XH1     67584                 // X half1 (single): hi 16K + lo 16K
#define SMEM_WBUF0   100352                // weight buf 0: hi 32K + lo 32K
#define SMEM_WBUF1   165888                // weight buf 1
#define SMEM_YBUF    100352                // overlays WBUF0 (free during final epi)
#define SMEM_TOTAL   231424

// Pre-split, pre-swizzled weights: [gemm][hi/lo][128*128] bf16
__device__ __align__(128) __nv_bfloat16 g_W[NGEMM][2][FDIM * FDIM];

// ---------------- PTX helpers (base sm_90 / sm_80 features only) ----------------
__device__ __forceinline__ uint32_t smem_u32(const void* p) {
    uint32_t a;
    asm("{ .reg .u64 t; cvta.to.shared.u64 t, %1; cvt.u32.u64 %0, t; }" : "=r"(a) : "l"(p));
    return a;
}
#define MBAR_INIT(mbar, cnt) \
    asm volatile("mbarrier.init.shared.b64 [%0], %1;" :: "r"(mbar), "r"(cnt) : "memory")
#define MBAR_EXPECT_TX(mbar, bytes) \
    asm volatile("mbarrier.arrive.expect_tx.shared.b64 _, [%0], %1;" :: "r"(mbar), "r"(bytes) : "memory")
#define MBAR_WAIT(mbar, ph) do {                                              \
    asm volatile("{\n\t.reg .pred P1;\n\t"                                    \
        "WL_%=:\n\t"                                                          \
        "mbarrier.try_wait.parity.acquire.cta.shared::cta.b64 P1, [%0], %1, 0x989680;\n\t" \
        "@P1 bra.uni WD_%=;\n\t"                                              \
        "bra.uni WL_%=;\n\t"                                                  \
        "WD_%=:\n\t}"                                                         \
        :: "r"(mbar), "r"(ph) : "memory");                                    \
} while (0)
#define BULK_G2S(dst, src, bytes, mbar) \
    asm volatile("cp.async.bulk.shared::cluster.global.mbarrier::complete_tx::bytes [%0], [%1], %2, [%3];" \
        :: "r"(dst), "l"(src), "r"(bytes), "r"(mbar) : "memory")

#define LDSM_X4(r, addr) \
    asm volatile("ldmatrix.sync.aligned.m8n8.x4.shared.b16 {%0,%1,%2,%3}, [%4];" \
        : "=r"((r)[0]), "=r"((r)[1]), "=r"((r)[2]), "=r"((r)[3]) : "r"(addr))
#define LDSM_X4T(r, addr) \
    asm volatile("ldmatrix.sync.aligned.m8n8.x4.trans.shared.b16 {%0,%1,%2,%3}, [%4];" \
        : "=r"((r)[0]), "=r"((r)[1]), "=r"((r)[2]), "=r"((r)[3]) : "r"(addr))

#define MMA16816(d, a, b0, b1) \
    asm volatile("mma.sync.aligned.m16n8k16.row.col.f32.bf16.bf16.f32 " \
        "{%0,%1,%2,%3},{%4,%5,%6,%7},{%8,%9},{%0,%1,%2,%3};" \
        : "+f"((d)[0]), "+f"((d)[1]), "+f"((d)[2]), "+f"((d)[3]) \
        : "r"((a)[0]), "r"((a)[1]), "r"((a)[2]), "r"((a)[3]), "r"(b0), "r"(b1))

// Weight tile: rows 256 B (128 bf16), XOR swizzle
__device__ __forceinline__ uint32_t woff(int f, int k) {
    return (uint32_t)(f * 256 + ((2 * k) ^ ((f & 7) << 4)));
}
// Activation half-tile: rows 128 B (64 bf16), XOR swizzle (n local 0..63)
__device__ __forceinline__ uint32_t xo64(int f, int n) {
    return (uint32_t)(f * 128 + ((2 * n) ^ ((f & 7) << 4)));
}

// split fp32 -> bf16 hi/lo and store pair (n,n+1) into a half-tile buffer
__device__ __forceinline__ void store_split64(char* xb, int f, int n, float v0, float v1) {
    uint32_t off = xo64(f, n);
    __nv_bfloat162 hi = __floats2bfloat162_rn(v0, v1);
    float r0 = v0 - __low2float(hi);
    float r1 = v1 - __high2float(hi);
    __nv_bfloat162 lo = __floats2bfloat162_rn(r0, r1);
    *reinterpret_cast<__nv_bfloat162*>(xb + off) = hi;
    *reinterpret_cast<__nv_bfloat162*>(xb + 16384 + off) = lo;
}

// ---------------- weight prep: fp32 -> split bf16 hi/lo, swizzled ----------------
__global__ void prep_weights_kernel(const float* __restrict__ W1,
                                    const float* __restrict__ W2) {
    int g = blockIdx.x;
    int layer = g >> 1;
    const float* src = ((g & 1) ? W2 : W1) + layer * FDIM * FDIM;
    for (int idx = threadIdx.x; idx < FDIM * FDIM; idx += blockDim.x) {
        int f = idx >> 7;
        int k = idx & 127;
        float w = src[idx];
        __nv_bfloat16 hi = __float2bfloat16(w);
        __nv_bfloat16 lo = __float2bfloat16(w - __bfloat162float(hi));
        uint32_t e = (uint32_t)(f * FDIM + (k ^ ((f & 7) << 3)));
        g_W[g][0][e] = hi;
        g_W[g][1][e] = lo;
    }
}

// One half-GEMM: 8 k-steps, fills dd[0..7] (8 m16n8 tiles over 64 points).
__device__ __forceinline__ void mma_half(uint32_t wbase, uint32_t xbase,
                                         float (*dd)[4], int f0, int li, int lr) {
#pragma unroll
    for (int kk = 0; kk < 8; kk++) {
        const int k0 = kk << 4;
        const int arow = f0 + ((li & 1) << 3) + lr;
        const int acol = k0 + ((li >> 1) << 3);
        const uint32_t aoff = woff(arow, acol);
        uint32_t ahi[4], alo[4];
        LDSM_X4(ahi, wbase + aoff);
        LDSM_X4(alo, wbase + 32768u + aoff);
        const int krow = k0 + ((li & 1) << 3) + lr;
        uint32_t bh[4][4], bl[4][4];
#pragma unroll
        for (int q = 0; q < 4; q++) {
            const int ncol = q * 16 + ((li >> 1) << 3);
            const uint32_t boff = xo64(krow, ncol);
            LDSM_X4T(bh[q], xbase + boff);
            LDSM_X4T(bl[q], xbase + 16384u + boff);
        }
#pragma unroll
        for (int q = 0; q < 4; q++) {
            MMA16816(dd[2 * q],     ahi, bh[q][0], bh[q][1]);
            MMA16816(dd[2 * q + 1], ahi, bh[q][2], bh[q][3]);
            MMA16816(dd[2 * q],     ahi, bl[q][0], bl[q][1]);
            MMA16816(dd[2 * q + 1], ahi, bl[q][2], bl[q][3]);
            MMA16816(dd[2 * q],     alo, bh[q][0], bh[q][1]);
            MMA16816(dd[2 * q + 1], alo, bh[q][2], bh[q][3]);
        }
    }
}

// ---------------- main kernel ----------------
__global__ __launch_bounds__(NTHR, 1)
void siren_mma_kernel(const float* __restrict__ coords,
                      const float* __restrict__ W_first,
                      const float* __restrict__ b_first,
                      const float* __restrict__ b1,
                      const float* __restrict__ b2,
                      const float* __restrict__ W_out,
                      const float* __restrict__ b_out,
                      float* __restrict__ out, int N) {
    extern __shared__ char smem[];
    const uint32_t sb = smem_u32(smem);
    float* cs = (float*)(smem + SMEM_CS);

    const int tid  = threadIdx.x;
    const int w    = tid >> 5;
    const int lane = tid & 31;
    const int f0   = w << 4;
    const int tg   = lane >> 2;
    const int t4   = lane & 3;
    const int r0   = f0 + tg;
    const int r1   = r0 + 8;
    const int P0   = blockIdx.x * TP;
    const int li   = lane >> 3;
    const int lr   = lane & 7;

    if (tid == 0) {
        MBAR_INIT(sb + SMEM_MB_W0, 1);
        MBAR_INIT(sb + SMEM_MB_W1, 1);
    }
    for (int t = tid; t < 3 * TP; t += NTHR) {
        int p = t / 3, d = t - p * 3;
        int pg = min(P0 + p, N - 1);
        cs[t] = coords[pg * 3 + d];
    }
    __syncthreads();

    if (tid == 0) {
        MBAR_EXPECT_TX(sb + SMEM_MB_W0, 65536u);
        BULK_G2S(sb + SMEM_WBUF0, (const void*)&g_W[0][0][0], 65536u, sb + SMEM_MB_W0);
        MBAR_EXPECT_TX(sb + SMEM_MB_W1, 65536u);
        BULK_G2S(sb + SMEM_WBUF1, (const void*)&g_W[1][0][0], 65536u, sb + SMEM_MB_W1);
    }

    float h[16][4];

    // ---- first layer: h = sin(30*(W_first x + b_first)) ----
    {
        const float wa0 = __ldg(&W_first[r0 * 3]), wa1 = __ldg(&W_first[r0 * 3 + 1]),
                    wa2 = __ldg(&W_first[r0 * 3 + 2]);
        const float wb0 = __ldg(&W_first[r1 * 3]), wb1 = __ldg(&W_first[r1 * 3 + 1]),
                    wb2 = __ldg(&W_first[r1 * 3 + 2]);
        const float ba = __ldg(&b_first[r0]), bb = __ldg(&b_first[r1]);
#pragma unroll
        for (int j = 0; j < 16; j++) {
            int pb = 8 * j + t4 * 2;
            float x0 = cs[pb * 3], y0 = cs[pb * 3 + 1], z0 = cs[pb * 3 + 2];
            float x1 = cs[pb * 3 + 3], y1 = cs[pb * 3 + 4], z1 = cs[pb * 3 + 5];
            h[j][0] = __sinf(OMEGA_W * fmaf(wa0, x0, fmaf(wa1, y0, fmaf(wa2, z0, ba))));
            h[j][1] = __sinf(OMEGA_W * fmaf(wa0, x1, fmaf(wa1, y1, fmaf(wa2, z1, ba))));
            h[j][2] = __sinf(OMEGA_W * fmaf(wb0, x0, fmaf(wb1, y0, fmaf(wb2, z0, bb))));
            h[j][3] = __sinf(OMEGA_W * fmaf(wb0, x1, fmaf(wb1, y1, fmaf(wb2, z1, bb))));
            char* xb = (j < 8) ? (smem + SMEM_XH0A) : (smem + SMEM_XH1);
            int nl = (j < 8) ? pb : (pb - 64);
            store_split64(xb, r0, nl, h[j][0], h[j][1]);
            store_split64(xb, r1, nl, h[j][2], h[j][3]);
        }
    }
    __syncthreads();

    int wph0 = 0, wph1 = 0;

    for (int g = 0; g < NGEMM; g++) {
        const int layer = g >> 1;
        const bool even = ((g & 1) == 0);

        {   // wait for this GEMM's weight buffer
            uint32_t mb = sb + ((g & 1) ? SMEM_MB_W1 : SMEM_MB_W0);
            int ph = (g & 1) ? wph1 : wph0;
            MBAR_WAIT(mb, ph);
            if (g & 1) wph1 ^= 1; else wph0 ^= 1;
        }

        const uint32_t wbase = sb + ((g & 1) ? SMEM_WBUF1 : SMEM_WBUF0);
        const uint32_t x0r = sb + ((g & 1) ? SMEM_XH0B : SMEM_XH0A);
        char* x0w = smem + ((g & 1) ? SMEM_XH0A : SMEM_XH0B);
        const uint32_t x1r = sb + SMEM_XH1;
        char* x1w = smem + SMEM_XH1;

        float d[16][4];
#pragma unroll
        for (int j = 0; j < 16; j++) { d[j][0] = d[j][1] = d[j][2] = d[j][3] = 0.f; }

        // biases for this GEMM's epilogue
        float ba, bb, w_in = 1.0f;
        if (even) {
            ba = __ldg(&b1[layer * FDIM + r0]);
            bb = __ldg(&b1[layer * FDIM + r1]);
            w_in = (layer > 0) ? 0.5f : 1.0f;
        } else {
            ba = __ldg(&b2[layer * FDIM + r0]);
            bb = __ldg(&b2[layer * FDIM + r1]);
        }

        // ---- phase 1: MMA(g, H0) ----
        mma_half(wbase, x0r, &d[0], f0, li, lr);

        if (g < NGEMM - 1) {
            // ---- phase 2: MMA(g, H1) interleaved with epi(g, H0) -> x0w ----
#pragma unroll
            for (int kk = 0; kk < 8; kk++) {
                const int k0 = kk << 4;
                const int arow = f0 + ((li & 1) << 3) + lr;
                const int acol = k0 + ((li >> 1) << 3);
                const uint32_t aoff = woff(arow, acol);
                uint32_t ahi[4], alo[4];
                LDSM_X4(ahi, wbase + aoff);
                LDSM_X4(alo, wbase + 32768u + aoff);
                const int krow = k0 + ((li & 1) << 3) + lr;
                uint32_t bh[4][4], bl[4][4];
#pragma unroll
                for (int q = 0; q < 4; q++) {
                    const int ncol = q * 16 + ((li >> 1) << 3);
                    const uint32_t boff = xo64(krow, ncol);
                    LDSM_X4T(bh[q], x1r + boff);
                    LDSM_X4T(bl[q], x1r + 16384u + boff);
                }
#pragma unroll
                for (int q = 0; q < 4; q++) {
                    float (*dd)[4] = &d[8];
                    MMA16816(dd[2 * q],     ahi, bh[q][0], bh[q][1]);
                    MMA16816(dd[2 * q + 1], ahi, bh[q][2], bh[q][3]);
                    MMA16816(dd[2 * q],     ahi, bl[q][0], bl[q][1]);
                    MMA16816(dd[2 * q + 1], ahi, bl[q][2], bl[q][3]);
                    MMA16816(dd[2 * q],     alo, bh[q][0], bh[q][1]);
                    MMA16816(dd[2 * q + 1], alo, bh[q][2], bh[q][3]);
                }
                // interleaved epilogue: H0 tile j = kk (independent of the MMAs above)
                {
                    const int j = kk;
                    const int pb = 8 * j + t4 * 2;
                    if (even) {
                        float s00 = __sinf(OMEGA_W * fmaf(w_in, d[j][0], ba));
                        float s01 = __sinf(OMEGA_W * fmaf(w_in, d[j][1], ba));
                        float s10 = __sinf(OMEGA_W * fmaf(w_in, d[j][2], bb));
                        float s11 = __sinf(OMEGA_W * fmaf(w_in, d[j][3], bb));
                        store_split64(x0w, r0, pb, s00, s01);
                        store_split64(x0w, r1, pb, s10, s11);
                    } else {
                        h[j][0] += __sinf(OMEGA_W * (d[j][0] + ba));
                        h[j][1] += __sinf(OMEGA_W * (d[j][1] + ba));
                        h[j][2] += __sinf(OMEGA_W * (d[j][2] + bb));
                        h[j][3] += __sinf(OMEGA_W * (d[j][3] + bb));
                        store_split64(x0w, r0, pb, h[j][0], h[j][1]);
                        store_split64(x0w, r1, pb, h[j][2], h[j][3]);
                    }
                }
            }
            __syncthreads();   // B: all MMA(g,*) done; W(g) + XH1 reads complete

            if (tid == 0 && g + 2 < NGEMM) {
                uint32_t mb = sb + ((g & 1) ? SMEM_MB_W1 : SMEM_MB_W0);
                uint32_t wb = sb + ((g & 1) ? SMEM_WBUF1 : SMEM_WBUF0);
                MBAR_EXPECT_TX(mb, 65536u);
                BULK_G2S(wb, (const void*)&g_W[g + 2][0][0], 65536u, mb);
            }

            // ---- epi(g, H1) -> XH1 (single buffer, protected by barrier B) ----
#pragma unroll
            for (int j = 8; j < 16; j++) {
                const int pb = 8 * j + t4 * 2;
                const int nl = pb - 64;
                if (even) {
                    float s00 = __sinf(OMEGA_W * fmaf(w_in, d[j][0], ba));
                    float s01 = __sinf(OMEGA_W * fmaf(w_in, d[j][1], ba));
                    float s10 = __sinf(OMEGA_W * fmaf(w_in, d[j][2], bb));
                    float s11 = __sinf(OMEGA_W * fmaf(w_in, d[j][3], bb));
                    store_split64(x1w, r0, nl, s00, s01);
                    store_split64(x1w, r1, nl, s10, s11);
                } else {
                    h[j][0] += __sinf(OMEGA_W * (d[j][0] + ba));
                    h[j][1] += __sinf(OMEGA_W * (d[j][1] + ba));
                    h[j][2] += __sinf(OMEGA_W * (d[j][2] + bb));
                    h[j][3] += __sinf(OMEGA_W * (d[j][3] + bb));
                    store_split64(x1w, r0, nl, h[j][0], h[j][1]);
                    store_split64(x1w, r1, nl, h[j][2], h[j][3]);
                }
            }
            __syncthreads();   // A: XH0[1-gp] + XH1 writes visible for g+1
        } else {
            // ---- last GEMM: plain MMA(H1), then final epilogue + output GEMV ----
            mma_half(wbase, x1r, &d[8], f0, li, lr);
            __syncthreads();   // WBUF0 (ybuf overlay) free; all MMA done

            const float wo0 = __ldg(&W_out[r0]), wo1 = __ldg(&W_out[r1]);
            float* ybuf = (float*)(smem + SMEM_YBUF);
#pragma unroll
            for (int j = 0; j < 16; j++) {
                float h0 = 0.5f * (h[j][0] + __sinf(OMEGA_W * (d[j][0] + ba)));
                float h1 = 0.5f * (h[j][1] + __sinf(OMEGA_W * (d[j][1] + ba)));
                float h2 = 0.5f * (h[j][2] + __sinf(OMEGA_W * (d[j][2] + bb)));
                float h3 = 0.5f * (h[j][3] + __sinf(OMEGA_W * (d[j][3] + bb)));
                float p0 = fmaf(h0, wo0, h2 * wo1);
                float p1 = fmaf(h1, wo0, h3 * wo1);
#pragma unroll
                for (int m = 4; m <= 16; m <<= 1) {
                    p0 += __shfl_xor_sync(0xffffffffu, p0, m);
                    p1 += __shfl_xor_sync(0xffffffffu, p1, m);
                }
                if (tg == 0) {
                    int p = 8 * j + t4 * 2;
                    *reinterpret_cast<float2*>(&ybuf[w * TP + p]) = make_float2(p0, p1);
                }
            }
            __syncthreads();
        }
    }

    // ---- cross-warp output reduction ----
    if (tid < TP) {
        int p = tid;
        if (P0 + p < N) {
            float* ybuf = (float*)(smem + SMEM_YBUF);
            float y = __ldg(&b_out[0]);
#pragma unroll
            for (int ww = 0; ww < 8; ww++) y += ybuf[ww * TP + p];
            out[P0 + p] = y;
        }
    }
}

extern "C" void kernel_launch(void* const* d_in, const int* in_sizes, int n_in,
                              void* d_out, int out_size) {
    const float* coords  = (const float*)d_in[0];
    const float* W_first = (const float*)d_in[1];
    const float* b_first = (const float*)d_in[2];
    const float* W1      = (const float*)d_in[3];
    const float* b1      = (const float*)d_in[4];
    const float* W2      = (const float*)d_in[5];
    const float* b2      = (const float*)d_in[6];
    const float* W_out   = (const float*)d_in[7];
    const float* b_out   = (const float*)d_in[8];
    const int N = in_sizes[0] / 3;

    prep_weights_kernel<<<NGEMM, 256>>>(W1, W2);

    cudaFuncSetAttribute(siren_mma_kernel,
                         cudaFuncAttributeMaxDynamicSharedMemorySize, SMEM_TOTAL);

    const int nblocks = (N + TP - 1) / TP;
    siren_mma_kernel<<<nblocks, NTHR, SMEM_TOTAL>>>(coords, W_first, b_first,
                                                    b1, b2, W_out, b_out,
                                                    (float*)d_out, N);
}

// round 6
// speedup vs baseline: 2.8531x; 1.0255x over previous
#include <cuda_runtime.h>
#include <cuda_bf16.h>
#include <cstdint>

#define FDIM    128
#define TP      128
#define NTHR    256
#define NLAYERS 8
#define NGEMM   16
#define OMEGA_W 30.0f

// ---------------- smem layout (bytes) ----------------
#define SMEM_MB_W0   0
#define SMEM_MB_W1   8
#define SMEM_CNT     16                    // 16 int counters (W consumption)
#define SMEM_CS      128                   // 128*3 floats coords (1536 B)
#define SMEM_YBUF    2048                  // [2][4][64] floats (2 KB)
#define SMEM_X       4096                  // X half0: hi 16K + lo 16K; half1 same
#define SMEM_WBUF0   69632                 // weight buf 0: hi 32K + lo 32K
#define SMEM_WBUF1   135168                // weight buf 1
#define SMEM_TOTAL   200704

// Pre-split, pre-swizzled weights: [gemm][hi/lo][128*128] bf16
__device__ __align__(128) __nv_bfloat16 g_W[NGEMM][2][FDIM * FDIM];

// ---------------- PTX helpers ----------------
__device__ __forceinline__ uint32_t smem_u32(const void* p) {
    uint32_t a;
    asm("{ .reg .u64 t; cvta.to.shared.u64 t, %1; cvt.u32.u64 %0, t; }" : "=r"(a) : "l"(p));
    return a;
}
#define MBAR_INIT(mbar, cnt) \
    asm volatile("mbarrier.init.shared.b64 [%0], %1;" :: "r"(mbar), "r"(cnt) : "memory")
#define MBAR_EXPECT_TX(mbar, bytes) \
    asm volatile("mbarrier.arrive.expect_tx.shared.b64 _, [%0], %1;" :: "r"(mbar), "r"(bytes) : "memory")
#define MBAR_WAIT(mbar, ph) do {                                              \
    asm volatile("{\n\t.reg .pred P1;\n\t"                                    \
        "WL_%=:\n\t"                                                          \
        "mbarrier.try_wait.parity.acquire.cta.shared::cta.b64 P1, [%0], %1, 0x989680;\n\t" \
        "@P1 bra.uni WD_%=;\n\t"                                              \
        "bra.uni WL_%=;\n\t"                                                  \
        "WD_%=:\n\t}"                                                         \
        :: "r"(mbar), "r"(ph) : "memory");                                    \
} while (0)
#define BULK_G2S(dst, src, bytes, mbar) \
    asm volatile("cp.async.bulk.shared::cluster.global.mbarrier::complete_tx::bytes [%0], [%1], %2, [%3];" \
        :: "r"(dst), "l"(src), "r"(bytes), "r"(mbar) : "memory")
#define BAR_HALF(id) asm volatile("bar.sync %0, 128;" :: "r"(id) : "memory")

#define LDSM_X4(r, addr) \
    asm volatile("ldmatrix.sync.aligned.m8n8.x4.shared.b16 {%0,%1,%2,%3}, [%4];" \
        : "=r"((r)[0]), "=r"((r)[1]), "=r"((r)[2]), "=r"((r)[3]) : "r"(addr))
#define LDSM_X4T(r, addr) \
    asm volatile("ldmatrix.sync.aligned.m8n8.x4.trans.shared.b16 {%0,%1,%2,%3}, [%4];" \
        : "=r"((r)[0]), "=r"((r)[1]), "=r"((r)[2]), "=r"((r)[3]) : "r"(addr))

#define MMA16816(d, a, b0, b1) \
    asm volatile("mma.sync.aligned.m16n8k16.row.col.f32.bf16.bf16.f32 " \
        "{%0,%1,%2,%3},{%4,%5,%6,%7},{%8,%9},{%0,%1,%2,%3};" \
        : "+f"((d)[0]), "+f"((d)[1]), "+f"((d)[2]), "+f"((d)[3]) \
        : "r"((a)[0]), "r"((a)[1]), "r"((a)[2]), "r"((a)[3]), "r"(b0), "r"(b1))

// Weight tile: rows 256 B (128 bf16), XOR swizzle
__device__ __forceinline__ uint32_t woff(int f, int k) {
    return (uint32_t)(f * 256 + ((2 * k) ^ ((f & 7) << 4)));
}
// Activation half-tile: rows 128 B (64 bf16), XOR swizzle
__device__ __forceinline__ uint32_t xo64(int f, int n) {
    return (uint32_t)(f * 128 + ((2 * n) ^ ((f & 7) << 4)));
}
__device__ __forceinline__ void store_split64(char* xb, int f, int n, float v0, float v1) {
    uint32_t off = xo64(f, n);
    __nv_bfloat162 hi = __floats2bfloat162_rn(v0, v1);
    float r0 = v0 - __low2float(hi);
    float r1 = v1 - __high2float(hi);
    __nv_bfloat162 lo = __floats2bfloat162_rn(r0, r1);
    *reinterpret_cast<__nv_bfloat162*>(xb + off) = hi;
    *reinterpret_cast<__nv_bfloat162*>(xb + 16384 + off) = lo;
}

// ---------------- weight prep ----------------
__global__ void prep_weights_kernel(const float* __restrict__ W1,
                                    const float* __restrict__ W2) {
    int g = blockIdx.x;
    int layer = g >> 1;
    const float* src = ((g & 1) ? W2 : W1) + layer * FDIM * FDIM;
    for (int idx = threadIdx.x; idx < FDIM * FDIM; idx += blockDim.x) {
        int f = idx >> 7;
        int k = idx & 127;
        float w = src[idx];
        __nv_bfloat16 hi = __float2bfloat16(w);
        __nv_bfloat16 lo = __float2bfloat16(w - __bfloat162float(hi));
        uint32_t e = (uint32_t)(f * FDIM + (k ^ ((f & 7) << 3)));
        g_W[g][0][e] = hi;
        g_W[g][1][e] = lo;
    }
}

// ---------------- main kernel ----------------
__global__ __launch_bounds__(NTHR, 1)
void siren_mma_kernel(const float* __restrict__ coords,
                      const float* __restrict__ W_first,
                      const float* __restrict__ b_first,
                      const float* __restrict__ b1,
                      const float* __restrict__ b2,
                      const float* __restrict__ W_out,
                      const float* __restrict__ b_out,
                      float* __restrict__ out, int N) {
    extern __shared__ char smem[];
    const uint32_t sb = smem_u32(smem);
    float* cs = (float*)(smem + SMEM_CS);
    int* cnt = (int*)(smem + SMEM_CNT);

    const int tid  = threadIdx.x;
    const int w    = tid >> 5;
    const int lane = tid & 31;
    const int wm   = w & 3;                // M group: features [32*wm, 32*wm+32)
    const int hf   = w >> 2;               // point half 0/1
    const int f0   = wm << 5;
    const int n0   = hf << 6;              // global point base in tile
    const int tg   = lane >> 2;
    const int t4   = lane & 3;
    const int li   = lane >> 3;
    const int lr   = lane & 7;
    const int P0   = blockIdx.x * TP;
    const int barid = 1 + hf;

    char* xb = smem + SMEM_X + hf * 32768;          // this half's X (hi; lo at +16K)
    const uint32_t xbu = sb + SMEM_X + hf * 32768;

    if (tid == 0) {
        MBAR_INIT(sb + SMEM_MB_W0, 1);
        MBAR_INIT(sb + SMEM_MB_W1, 1);
    }
    if (tid < NGEMM) cnt[tid] = 0;
    for (int t = tid; t < 3 * TP; t += NTHR) {
        int p = t / 3, d = t - p * 3;
        int pg = min(P0 + p, N - 1);
        cs[t] = coords[pg * 3 + d];
    }
    __syncthreads();

    if (tid == 0) {
        MBAR_EXPECT_TX(sb + SMEM_MB_W0, 65536u);
        BULK_G2S(sb + SMEM_WBUF0, (const void*)&g_W[0][0][0], 65536u, sb + SMEM_MB_W0);
        MBAR_EXPECT_TX(sb + SMEM_MB_W1, 65536u);
        BULK_G2S(sb + SMEM_WBUF1, (const void*)&g_W[1][0][0], 65536u, sb + SMEM_MB_W1);
    }

    // rows this thread owns: f0 + 16*mi + tg (+8)
    float h[2][8][4];                      // residual  [mi][ni][c]

    // ---- first layer ----
    {
#pragma unroll
        for (int mi = 0; mi < 2; mi++) {
            const int ra = f0 + 16 * mi + tg, rb = ra + 8;
            const float wa0 = __ldg(&W_first[ra * 3]), wa1 = __ldg(&W_first[ra * 3 + 1]),
                        wa2 = __ldg(&W_first[ra * 3 + 2]);
            const float wb0 = __ldg(&W_first[rb * 3]), wb1 = __ldg(&W_first[rb * 3 + 1]),
                        wb2 = __ldg(&W_first[rb * 3 + 2]);
            const float ba = __ldg(&b_first[ra]), bb = __ldg(&b_first[rb]);
#pragma unroll
            for (int ni = 0; ni < 8; ni++) {
                const int nl = 8 * ni + t4 * 2;
                const int p = n0 + nl;
                float x0 = cs[p * 3], y0 = cs[p * 3 + 1], z0 = cs[p * 3 + 2];
                float x1 = cs[p * 3 + 3], y1 = cs[p * 3 + 4], z1 = cs[p * 3 + 5];
                h[mi][ni][0] = __sinf(OMEGA_W * fmaf(wa0, x0, fmaf(wa1, y0, fmaf(wa2, z0, ba))));
                h[mi][ni][1] = __sinf(OMEGA_W * fmaf(wa0, x1, fmaf(wa1, y1, fmaf(wa2, z1, ba))));
                h[mi][ni][2] = __sinf(OMEGA_W * fmaf(wb0, x0, fmaf(wb1, y0, fmaf(wb2, z0, bb))));
                h[mi][ni][3] = __sinf(OMEGA_W * fmaf(wb0, x1, fmaf(wb1, y1, fmaf(wb2, z1, bb))));
                store_split64(xb, ra, nl, h[mi][ni][0], h[mi][ni][1]);
                store_split64(xb, rb, nl, h[mi][ni][2], h[mi][ni][3]);
            }
        }
    }
    BAR_HALF(barid);

    int wph0 = 0, wph1 = 0;

    for (int g = 0; g < NGEMM; g++) {
        const int layer = g >> 1;
        const bool even = ((g & 1) == 0);

        {   // wait for this GEMM's weight buffer
            uint32_t mb = sb + ((g & 1) ? SMEM_MB_W1 : SMEM_MB_W0);
            int ph = (g & 1) ? wph1 : wph0;
            MBAR_WAIT(mb, ph);
            if (g & 1) wph1 ^= 1; else wph0 ^= 1;
        }

        const uint32_t wbase = sb + ((g & 1) ? SMEM_WBUF1 : SMEM_WBUF0);

        float d[2][8][4];
#pragma unroll
        for (int mi = 0; mi < 2; mi++)
#pragma unroll
            for (int ni = 0; ni < 8; ni++)
                d[mi][ni][0] = d[mi][ni][1] = d[mi][ni][2] = d[mi][ni][3] = 0.f;

        // ---- MMA: product-major order, same-acc distance 16 ----
#pragma unroll
        for (int kk = 0; kk < 8; kk++) {
            const int k0 = kk << 4;
            uint32_t ahi[2][4], alo[2][4];
#pragma unroll
            for (int mi = 0; mi < 2; mi++) {
                const int arow = f0 + 16 * mi + ((li & 1) << 3) + lr;
                const int acol = k0 + ((li >> 1) << 3);
                const uint32_t aoff = woff(arow, acol);
                LDSM_X4(ahi[mi], wbase + aoff);
                LDSM_X4(alo[mi], wbase + 32768u + aoff);
            }
            const int krow = k0 + ((li & 1) << 3) + lr;
            uint32_t bh[4][4], bl[4][4];
#pragma unroll
            for (int q = 0; q < 4; q++) {
                const int ncol = q * 16 + ((li >> 1) << 3);
                const uint32_t boff = xo64(krow, ncol);
                LDSM_X4T(bh[q], xbu + boff);
                LDSM_X4T(bl[q], xbu + 16384u + boff);
            }
            // product 0: Whi * Xhi (16 MMAs, all accs distinct)
#pragma unroll
            for (int mi = 0; mi < 2; mi++)
#pragma unroll
                for (int q = 0; q < 4; q++) {
                    MMA16816(d[mi][2 * q],     ahi[mi], bh[q][0], bh[q][1]);
                    MMA16816(d[mi][2 * q + 1], ahi[mi], bh[q][2], bh[q][3]);
                }
            // product 1: Whi * Xlo
#pragma unroll
            for (int mi = 0; mi < 2; mi++)
#pragma unroll
                for (int q = 0; q < 4; q++) {
                    MMA16816(d[mi][2 * q],     ahi[mi], bl[q][0], bl[q][1]);
                    MMA16816(d[mi][2 * q + 1], ahi[mi], bl[q][2], bl[q][3]);
                }
            // product 2: Wlo * Xhi
#pragma unroll
            for (int mi = 0; mi < 2; mi++)
#pragma unroll
                for (int q = 0; q < 4; q++) {
                    MMA16816(d[mi][2 * q],     alo[mi], bh[q][0], bh[q][1]);
                    MMA16816(d[mi][2 * q + 1], alo[mi], bh[q][2], bh[q][3]);
                }
        }

        // W(g) consumption tracking; last warp chip-wide launches prefetch of g+2
        if (lane == 0) {
            int old = atomicAdd(&cnt[g], 1);
            if (old == 7 && g + 2 < NGEMM) {
                uint32_t mb = sb + ((g & 1) ? SMEM_MB_W1 : SMEM_MB_W0);
                uint32_t wbuf = sb + ((g & 1) ? SMEM_WBUF1 : SMEM_WBUF0);
                MBAR_EXPECT_TX(mb, 65536u);
                BULK_G2S(wbuf, (const void*)&g_W[g + 2][0][0], 65536u, mb);
            }
        }

        BAR_HALF(barid);   // all 4 warps of this half done reading X-half

        if (g < NGEMM - 1) {
            // ---- epilogue: write X-half in place ----
#pragma unroll
            for (int mi = 0; mi < 2; mi++) {
                const int ra = f0 + 16 * mi + tg, rb = ra + 8;
                float ba, bb;
                if (even) {
                    ba = __ldg(&b1[layer * FDIM + ra]);
                    bb = __ldg(&b1[layer * FDIM + rb]);
                } else {
                    ba = __ldg(&b2[layer * FDIM + ra]);
                    bb = __ldg(&b2[layer * FDIM + rb]);
                }
                const float w_in = (even && layer > 0) ? 0.5f : 1.0f;
#pragma unroll
                for (int ni = 0; ni < 8; ni++) {
                    const int nl = 8 * ni + t4 * 2;
                    if (even) {
                        float s00 = __sinf(OMEGA_W * fmaf(w_in, d[mi][ni][0], ba));
                        float s01 = __sinf(OMEGA_W * fmaf(w_in, d[mi][ni][1], ba));
                        float s10 = __sinf(OMEGA_W * fmaf(w_in, d[mi][ni][2], bb));
                        float s11 = __sinf(OMEGA_W * fmaf(w_in, d[mi][ni][3], bb));
                        store_split64(xb, ra, nl, s00, s01);
                        store_split64(xb, rb, nl, s10, s11);
                    } else {
                        h[mi][ni][0] += __sinf(OMEGA_W * (d[mi][ni][0] + ba));
                        h[mi][ni][1] += __sinf(OMEGA_W * (d[mi][ni][1] + ba));
                        h[mi][ni][2] += __sinf(OMEGA_W * (d[mi][ni][2] + bb));
                        h[mi][ni][3] += __sinf(OMEGA_W * (d[mi][ni][3] + bb));
                        store_split64(xb, ra, nl, h[mi][ni][0], h[mi][ni][1]);
                        store_split64(xb, rb, nl, h[mi][ni][2], h[mi][ni][3]);
                    }
                }
            }
            BAR_HALF(barid);   // epilogue writes visible before next MMA
        } else {
            // ---- final epilogue: h = 0.5*(h+s2), output GEMV ----
            float* ybuf = (float*)(smem + SMEM_YBUF) + hf * 256;
            float p0s[8], p1s[8];
#pragma unroll
            for (int ni = 0; ni < 8; ni++) { p0s[ni] = 0.f; p1s[ni] = 0.f; }
#pragma unroll
            for (int mi = 0; mi < 2; mi++) {
                const int ra = f0 + 16 * mi + tg, rb = ra + 8;
                const float ba = __ldg(&b2[layer * FDIM + ra]);
                const float bb = __ldg(&b2[layer * FDIM + rb]);
                const float woa = __ldg(&W_out[ra]), wob = __ldg(&W_out[rb]);
#pragma unroll
                for (int ni = 0; ni < 8; ni++) {
                    float h0 = 0.5f * (h[mi][ni][0] + __sinf(OMEGA_W * (d[mi][ni][0] + ba)));
                    float h1 = 0.5f * (h[mi][ni][1] + __sinf(OMEGA_W * (d[mi][ni][1] + ba)));
                    float h2 = 0.5f * (h[mi][ni][2] + __sinf(OMEGA_W * (d[mi][ni][2] + bb)));
                    float h3 = 0.5f * (h[mi][ni][3] + __sinf(OMEGA_W * (d[mi][ni][3] + bb)));
                    p0s[ni] += fmaf(h0, woa, h2 * wob);
                    p1s[ni] += fmaf(h1, woa, h3 * wob);
                }
            }
#pragma unroll
            for (int ni = 0; ni < 8; ni++) {
                float p0 = p0s[ni], p1 = p1s[ni];
#pragma unroll
                for (int m = 4; m <= 16; m <<= 1) {
                    p0 += __shfl_xor_sync(0xffffffffu, p0, m);
                    p1 += __shfl_xor_sync(0xffffffffu, p1, m);
                }
                if (tg == 0) {
                    int nl = 8 * ni + t4 * 2;
                    *reinterpret_cast<float2*>(&ybuf[wm * 64 + nl]) = make_float2(p0, p1);
                }
            }
            BAR_HALF(barid);
        }
    }

    // ---- cross-warp output reduction (per half, 64 points) ----
    {
        const int lih = tid - hf * 128;    // 0..127 within half
        if (lih < 64) {
            int p = n0 + lih;
            if (P0 + p < N) {
                float* ybuf = (float*)(smem + SMEM_YBUF) + hf * 256;
                float y = __ldg(&b_out[0]) + ybuf[lih] + ybuf[64 + lih]
                        + ybuf[128 + lih] + ybuf[192 + lih];
                out[P0 + p] = y;
            }
        }
    }
}

extern "C" void kernel_launch(void* const* d_in, const int* in_sizes, int n_in,
                              void* d_out, int out_size) {
    const float* coords  = (const float*)d_in[0];
    const float* W_first = (const float*)d_in[1];
    const float* b_first = (const float*)d_in[2];
    const float* W1      = (const float*)d_in[3];
    const float* b1      = (const float*)d_in[4];
    const float* W2      = (const float*)d_in[5];
    const float* b2      = (const float*)d_in[6];
    const float* W_out   = (const float*)d_in[7];
    const float* b_out   = (const float*)d_in[8];
    const int N = in_sizes[0] / 3;

    prep_weights_kernel<<<NGEMM, 256>>>(W1, W2);

    cudaFuncSetAttribute(siren_mma_kernel,
                         cudaFuncAttributeMaxDynamicSharedMemorySize, SMEM_TOTAL);

    const int nblocks = (N + TP - 1) / TP;
    siren_mma_kernel<<<nblocks, NTHR, SMEM_TOTAL>>>(coords, W_first, b_first,
                                                    b1, b2, W_out, b_out,
                                                    (float*)d_out, N);
}

// round 7
// speedup vs baseline: 3.0453x; 1.0674x over previous
#include <cuda_runtime.h>
#include <cuda_bf16.h>
#include <cstdint>

#define FDIM    128
#define TP      128
#define NTHR    256
#define NLAYERS 8
#define NGEMM   16
#define OMEGA_W 30.0f
#define SKEW_CYC 2600u

// ---------------- smem layout (bytes) ----------------
#define SMEM_MB_W0   0
#define SMEM_MB_W1   8
#define SMEM_CNT     16                    // 16 int counters (W consumption)
#define SMEM_CS      128                   // 128*3 floats coords (1536 B)
#define SMEM_YBUF    2048                  // [2][4][64] floats (2 KB)
#define SMEM_X       4096                  // X half0: hi 16K + lo 16K; half1 same
#define SMEM_WBUF0   69632                 // weight buf 0: hi 32K + lo 32K
#define SMEM_WBUF1   135168                // weight buf 1
#define SMEM_TOTAL   200704

// Pre-split, pre-swizzled weights: [gemm][hi/lo][128*128] bf16
__device__ __align__(128) __nv_bfloat16 g_W[NGEMM][2][FDIM * FDIM];

// ---------------- PTX helpers ----------------
__device__ __forceinline__ uint32_t smem_u32(const void* p) {
    uint32_t a;
    asm("{ .reg .u64 t; cvta.to.shared.u64 t, %1; cvt.u32.u64 %0, t; }" : "=r"(a) : "l"(p));
    return a;
}
#define MBAR_INIT(mbar, cnt) \
    asm volatile("mbarrier.init.shared.b64 [%0], %1;" :: "r"(mbar), "r"(cnt) : "memory")
#define MBAR_EXPECT_TX(mbar, bytes) \
    asm volatile("mbarrier.arrive.expect_tx.shared.b64 _, [%0], %1;" :: "r"(mbar), "r"(bytes) : "memory")
#define MBAR_WAIT(mbar, ph) do {                                              \
    asm volatile("{\n\t.reg .pred P1;\n\t"                                    \
        "WL_%=:\n\t"                                                          \
        "mbarrier.try_wait.parity.acquire.cta.shared::cta.b64 P1, [%0], %1, 0x989680;\n\t" \
        "@P1 bra.uni WD_%=;\n\t"                                              \
        "bra.uni WL_%=;\n\t"                                                  \
        "WD_%=:\n\t}"                                                         \
        :: "r"(mbar), "r"(ph) : "memory");                                    \
} while (0)
#define BULK_G2S(dst, src, bytes, mbar) \
    asm volatile("cp.async.bulk.shared::cluster.global.mbarrier::complete_tx::bytes [%0], [%1], %2, [%3];" \
        :: "r"(dst), "l"(src), "r"(bytes), "r"(mbar) : "memory")
#define BAR_HALF(id) asm volatile("bar.sync %0, 128;" :: "r"(id) : "memory")

#define LDSM_X4(r, addr) \
    asm volatile("ldmatrix.sync.aligned.m8n8.x4.shared.b16 {%0,%1,%2,%3}, [%4];" \
        : "=r"((r)[0]), "=r"((r)[1]), "=r"((r)[2]), "=r"((r)[3]) : "r"(addr))
#define LDSM_X4T(r, addr) \
    asm volatile("ldmatrix.sync.aligned.m8n8.x4.trans.shared.b16 {%0,%1,%2,%3}, [%4];" \
        : "=r"((r)[0]), "=r"((r)[1]), "=r"((r)[2]), "=r"((r)[3]) : "r"(addr))

#define MMA16816(d, a, b0, b1) \
    asm volatile("mma.sync.aligned.m16n8k16.row.col.f32.bf16.bf16.f32 " \
        "{%0,%1,%2,%3},{%4,%5,%6,%7},{%8,%9},{%0,%1,%2,%3};" \
        : "+f"((d)[0]), "+f"((d)[1]), "+f"((d)[2]), "+f"((d)[3]) \
        : "r"((a)[0]), "r"((a)[1]), "r"((a)[2]), "r"((a)[3]), "r"(b0), "r"(b1))

// Weight tile: rows 256 B (128 bf16), XOR swizzle
__device__ __forceinline__ uint32_t woff(int f, int k) {
    return (uint32_t)(f * 256 + ((2 * k) ^ ((f & 7) << 4)));
}
// Activation half-tile: rows 128 B (64 bf16), XOR swizzle
__device__ __forceinline__ uint32_t xo64(int f, int n) {
    return (uint32_t)(f * 128 + ((2 * n) ^ ((f & 7) << 4)));
}
__device__ __forceinline__ void store_split64(char* xb, int f, int n, float v0, float v1) {
    uint32_t off = xo64(f, n);
    __nv_bfloat162 hi = __floats2bfloat162_rn(v0, v1);
    float r0 = v0 - __low2float(hi);
    float r1 = v1 - __high2float(hi);
    __nv_bfloat162 lo = __floats2bfloat162_rn(r0, r1);
    *reinterpret_cast<__nv_bfloat162*>(xb + off) = hi;
    *reinterpret_cast<__nv_bfloat162*>(xb + 16384 + off) = lo;
}

// ---------------- weight prep ----------------
__global__ void prep_weights_kernel(const float* __restrict__ W1,
                                    const float* __restrict__ W2) {
    int g = blockIdx.x;
    int layer = g >> 1;
    const float* src = ((g & 1) ? W2 : W1) + layer * FDIM * FDIM;
    for (int idx = threadIdx.x; idx < FDIM * FDIM; idx += blockDim.x) {
        int f = idx >> 7;
        int k = idx & 127;
        float w = src[idx];
        __nv_bfloat16 hi = __float2bfloat16(w);
        __nv_bfloat16 lo = __float2bfloat16(w - __bfloat162float(hi));
        uint32_t e = (uint32_t)(f * FDIM + (k ^ ((f & 7) << 3)));
        g_W[g][0][e] = hi;
        g_W[g][1][e] = lo;
    }
}

// ---------------- main kernel ----------------
__global__ __launch_bounds__(NTHR, 1)
void siren_mma_kernel(const float* __restrict__ coords,
                      const float* __restrict__ W_first,
                      const float* __restrict__ b_first,
                      const float* __restrict__ b1,
                      const float* __restrict__ b2,
                      const float* __restrict__ W_out,
                      const float* __restrict__ b_out,
                      float* __restrict__ out, int N) {
    extern __shared__ char smem[];
    const uint32_t sb = smem_u32(smem);
    float* cs = (float*)(smem + SMEM_CS);
    int* cnt = (int*)(smem + SMEM_CNT);

    const int tid  = threadIdx.x;
    const int w    = tid >> 5;
    const int lane = tid & 31;
    const int wm   = w & 3;                // M group: features [32*wm, 32*wm+32)
    const int hf   = w >> 2;               // point half 0/1
    const int f0   = wm << 5;
    const int n0   = hf << 6;              // global point base in tile
    const int tg   = lane >> 2;
    const int t4   = lane & 3;
    const int li   = lane >> 3;
    const int lr   = lane & 7;
    const int P0   = blockIdx.x * TP;
    const int barid = 1 + hf;

    char* xb = smem + SMEM_X + hf * 32768;          // this half's X (hi; lo at +16K)
    const uint32_t xbu = sb + SMEM_X + hf * 32768;

    if (tid == 0) {
        MBAR_INIT(sb + SMEM_MB_W0, 1);
        MBAR_INIT(sb + SMEM_MB_W1, 1);
    }
    if (tid < NGEMM) cnt[tid] = 0;
    for (int t = tid; t < 3 * TP; t += NTHR) {
        int p = t / 3, d = t - p * 3;
        int pg = min(P0 + p, N - 1);
        cs[t] = coords[pg * 3 + d];
    }
    __syncthreads();

    if (tid == 0) {
        MBAR_EXPECT_TX(sb + SMEM_MB_W0, 65536u);
        BULK_G2S(sb + SMEM_WBUF0, (const void*)&g_W[0][0][0], 65536u, sb + SMEM_MB_W0);
        MBAR_EXPECT_TX(sb + SMEM_MB_W1, 65536u);
        BULK_G2S(sb + SMEM_WBUF1, (const void*)&g_W[1][0][0], 65536u, sb + SMEM_MB_W1);
    }

    // rows this thread owns: f0 + 16*mi + tg (+8)
    float h[2][8][4];                      // residual  [mi][ni][c]

    // ---- first layer ----
    {
#pragma unroll
        for (int mi = 0; mi < 2; mi++) {
            const int ra = f0 + 16 * mi + tg, rb = ra + 8;
            const float wa0 = __ldg(&W_first[ra * 3]), wa1 = __ldg(&W_first[ra * 3 + 1]),
                        wa2 = __ldg(&W_first[ra * 3 + 2]);
            const float wb0 = __ldg(&W_first[rb * 3]), wb1 = __ldg(&W_first[rb * 3 + 1]),
                        wb2 = __ldg(&W_first[rb * 3 + 2]);
            const float ba = __ldg(&b_first[ra]), bb = __ldg(&b_first[rb]);
#pragma unroll
            for (int ni = 0; ni < 8; ni++) {
                const int nl = 8 * ni + t4 * 2;
                const int p = n0 + nl;
                float x0 = cs[p * 3], y0 = cs[p * 3 + 1], z0 = cs[p * 3 + 2];
                float x1 = cs[p * 3 + 3], y1 = cs[p * 3 + 4], z1 = cs[p * 3 + 5];
                h[mi][ni][0] = __sinf(OMEGA_W * fmaf(wa0, x0, fmaf(wa1, y0, fmaf(wa2, z0, ba))));
                h[mi][ni][1] = __sinf(OMEGA_W * fmaf(wa0, x1, fmaf(wa1, y1, fmaf(wa2, z1, ba))));
                h[mi][ni][2] = __sinf(OMEGA_W * fmaf(wb0, x0, fmaf(wb1, y0, fmaf(wb2, z0, bb))));
                h[mi][ni][3] = __sinf(OMEGA_W * fmaf(wb0, x1, fmaf(wb1, y1, fmaf(wb2, z1, bb))));
                store_split64(xb, ra, nl, h[mi][ni][0], h[mi][ni][1]);
                store_split64(xb, rb, nl, h[mi][ni][2], h[mi][ni][3]);
            }
        }
    }
    BAR_HALF(barid);

    // ---- anti-phase skew: delay half 1 by ~one epilogue so its MMA phase
    // fills the tensor pipe while half 0 epilogues, and vice versa. The two
    // chains are rate-matched and only coupled through non-blocking waits,
    // so the skew persists for all 16 GEMMs. ----
    if (hf == 1) {
        uint32_t t0, t1;
        asm volatile("mov.u32 %0, %%clock;" : "=r"(t0));
        do {
            asm volatile("mov.u32 %0, %%clock;" : "=r"(t1));
        } while (t1 - t0 < SKEW_CYC);
    }

    int wph0 = 0, wph1 = 0;

    for (int g = 0; g < NGEMM; g++) {
        const int layer = g >> 1;
        const bool even = ((g & 1) == 0);

        {   // wait for this GEMM's weight buffer
            uint32_t mb = sb + ((g & 1) ? SMEM_MB_W1 : SMEM_MB_W0);
            int ph = (g & 1) ? wph1 : wph0;
            MBAR_WAIT(mb, ph);
            if (g & 1) wph1 ^= 1; else wph0 ^= 1;
        }

        const uint32_t wbase = sb + ((g & 1) ? SMEM_WBUF1 : SMEM_WBUF0);

        float d[2][8][4];
#pragma unroll
        for (int mi = 0; mi < 2; mi++)
#pragma unroll
            for (int ni = 0; ni < 8; ni++)
                d[mi][ni][0] = d[mi][ni][1] = d[mi][ni][2] = d[mi][ni][3] = 0.f;

        // ---- MMA: product-major order, same-acc distance 16 ----
#pragma unroll
        for (int kk = 0; kk < 8; kk++) {
            const int k0 = kk << 4;
            uint32_t ahi[2][4], alo[2][4];
#pragma unroll
            for (int mi = 0; mi < 2; mi++) {
                const int arow = f0 + 16 * mi + ((li & 1) << 3) + lr;
                const int acol = k0 + ((li >> 1) << 3);
                const uint32_t aoff = woff(arow, acol);
                LDSM_X4(ahi[mi], wbase + aoff);
                LDSM_X4(alo[mi], wbase + 32768u + aoff);
            }
            const int krow = k0 + ((li & 1) << 3) + lr;
            uint32_t bh[4][4], bl[4][4];
#pragma unroll
            for (int q = 0; q < 4; q++) {
                const int ncol = q * 16 + ((li >> 1) << 3);
                const uint32_t boff = xo64(krow, ncol);
                LDSM_X4T(bh[q], xbu + boff);
                LDSM_X4T(bl[q], xbu + 16384u + boff);
            }
#pragma unroll
            for (int mi = 0; mi < 2; mi++)
#pragma unroll
                for (int q = 0; q < 4; q++) {
                    MMA16816(d[mi][2 * q],     ahi[mi], bh[q][0], bh[q][1]);
                    MMA16816(d[mi][2 * q + 1], ahi[mi], bh[q][2], bh[q][3]);
                }
#pragma unroll
            for (int mi = 0; mi < 2; mi++)
#pragma unroll
                for (int q = 0; q < 4; q++) {
                    MMA16816(d[mi][2 * q],     ahi[mi], bl[q][0], bl[q][1]);
                    MMA16816(d[mi][2 * q + 1], ahi[mi], bl[q][2], bl[q][3]);
                }
#pragma unroll
            for (int mi = 0; mi < 2; mi++)
#pragma unroll
                for (int q = 0; q < 4; q++) {
                    MMA16816(d[mi][2 * q],     alo[mi], bh[q][0], bh[q][1]);
                    MMA16816(d[mi][2 * q + 1], alo[mi], bh[q][2], bh[q][3]);
                }
        }

        // W(g) consumption tracking; last warp chip-wide launches prefetch of g+2
        if (lane == 0) {
            int old = atomicAdd(&cnt[g], 1);
            if (old == 7 && g + 2 < NGEMM) {
                uint32_t mb = sb + ((g & 1) ? SMEM_MB_W1 : SMEM_MB_W0);
                uint32_t wbuf = sb + ((g & 1) ? SMEM_WBUF1 : SMEM_WBUF0);
                MBAR_EXPECT_TX(mb, 65536u);
                BULK_G2S(wbuf, (const void*)&g_W[g + 2][0][0], 65536u, mb);
            }
        }

        BAR_HALF(barid);   // all 4 warps of this half done reading X-half

        if (g < NGEMM - 1) {
            // ---- epilogue: write X-half in place ----
#pragma unroll
            for (int mi = 0; mi < 2; mi++) {
                const int ra = f0 + 16 * mi + tg, rb = ra + 8;
                float ba, bb;
                if (even) {
                    ba = __ldg(&b1[layer * FDIM + ra]);
                    bb = __ldg(&b1[layer * FDIM + rb]);
                } else {
                    ba = __ldg(&b2[layer * FDIM + ra]);
                    bb = __ldg(&b2[layer * FDIM + rb]);
                }
                const float w_in = (even && layer > 0) ? 0.5f : 1.0f;
#pragma unroll
                for (int ni = 0; ni < 8; ni++) {
                    const int nl = 8 * ni + t4 * 2;
                    if (even) {
                        float s00 = __sinf(OMEGA_W * fmaf(w_in, d[mi][ni][0], ba));
                        float s01 = __sinf(OMEGA_W * fmaf(w_in, d[mi][ni][1], ba));
                        float s10 = __sinf(OMEGA_W * fmaf(w_in, d[mi][ni][2], bb));
                        float s11 = __sinf(OMEGA_W * fmaf(w_in, d[mi][ni][3], bb));
                        store_split64(xb, ra, nl, s00, s01);
                        store_split64(xb, rb, nl, s10, s11);
                    } else {
                        h[mi][ni][0] += __sinf(OMEGA_W * (d[mi][ni][0] + ba));
                        h[mi][ni][1] += __sinf(OMEGA_W * (d[mi][ni][1] + ba));
                        h[mi][ni][2] += __sinf(OMEGA_W * (d[mi][ni][2] + bb));
                        h[mi][ni][3] += __sinf(OMEGA_W * (d[mi][ni][3] + bb));
                        store_split64(xb, ra, nl, h[mi][ni][0], h[mi][ni][1]);
                        store_split64(xb, rb, nl, h[mi][ni][2], h[mi][ni][3]);
                    }
                }
            }
            BAR_HALF(barid);   // epilogue writes visible before next MMA
        } else {
            // ---- final epilogue: h = 0.5*(h+s2), output GEMV ----
            float* ybuf = (float*)(smem + SMEM_YBUF) + hf * 256;
            float p0s[8], p1s[8];
#pragma unroll
            for (int ni = 0; ni < 8; ni++) { p0s[ni] = 0.f; p1s[ni] = 0.f; }
#pragma unroll
            for (int mi = 0; mi < 2; mi++) {
                const int ra = f0 + 16 * mi + tg, rb = ra + 8;
                const float ba = __ldg(&b2[layer * FDIM + ra]);
                const float bb = __ldg(&b2[layer * FDIM + rb]);
                const float woa = __ldg(&W_out[ra]), wob = __ldg(&W_out[rb]);
#pragma unroll
                for (int ni = 0; ni < 8; ni++) {
                    float h0 = 0.5f * (h[mi][ni][0] + __sinf(OMEGA_W * (d[mi][ni][0] + ba)));
                    float h1 = 0.5f * (h[mi][ni][1] + __sinf(OMEGA_W * (d[mi][ni][1] + ba)));
                    float h2 = 0.5f * (h[mi][ni][2] + __sinf(OMEGA_W * (d[mi][ni][2] + bb)));
                    float h3 = 0.5f * (h[mi][ni][3] + __sinf(OMEGA_W * (d[mi][ni][3] + bb)));
                    p0s[ni] += fmaf(h0, woa, h2 * wob);
                    p1s[ni] += fmaf(h1, woa, h3 * wob);
                }
            }
#pragma unroll
            for (int ni = 0; ni < 8; ni++) {
                float p0 = p0s[ni], p1 = p1s[ni];
#pragma unroll
                for (int m = 4; m <= 16; m <<= 1) {
                    p0 += __shfl_xor_sync(0xffffffffu, p0, m);
                    p1 += __shfl_xor_sync(0xffffffffu, p1, m);
                }
                if (tg == 0) {
                    int nl = 8 * ni + t4 * 2;
                    *reinterpret_cast<float2*>(&ybuf[wm * 64 + nl]) = make_float2(p0, p1);
                }
            }
            BAR_HALF(barid);
        }
    }

    // ---- cross-warp output reduction (per half, 64 points) ----
    {
        const int lih = tid - hf * 128;    // 0..127 within half
        if (lih < 64) {
            int p = n0 + lih;
            if (P0 + p < N) {
                float* ybuf = (float*)(smem + SMEM_YBUF) + hf * 256;
                float y = __ldg(&b_out[0]) + ybuf[lih] + ybuf[64 + lih]
                        + ybuf[128 + lih] + ybuf[192 + lih];
                out[P0 + p] = y;
            }
        }
    }
}

extern "C" void kernel_launch(void* const* d_in, const int* in_sizes, int n_in,
                              void* d_out, int out_size) {
    const float* coords  = (const float*)d_in[0];
    const float* W_first = (const float*)d_in[1];
    const float* b_first = (const float*)d_in[2];
    const float* W1      = (const float*)d_in[3];
    const float* b1      = (const float*)d_in[4];
    const float* W2      = (const float*)d_in[5];
    const float* b2      = (const float*)d_in[6];
    const float* W_out   = (const float*)d_in[7];
    const float* b_out   = (const float*)d_in[8];
    const int N = in_sizes[0] / 3;

    prep_weights_kernel<<<NGEMM, 256>>>(W1, W2);

    cudaFuncSetAttribute(siren_mma_kernel,
                         cudaFuncAttributeMaxDynamicSharedMemorySize, SMEM_TOTAL);

    const int nblocks = (N + TP - 1) / TP;
    siren_mma_kernel<<<nblocks, NTHR, SMEM_TOTAL>>>(coords, W_first, b_first,
                                                    b1, b2, W_out, b_out,
                                                    (float*)d_out, N);
}